// round 14
// baseline (speedup 1.0000x reference)
#include <cuda_runtime.h>
#include <cuda_fp16.h>
#include <cstdint>

// Problem (fixed): B=4,N=2048,Fin=128,H=4,Fout=32.
// Identity: softmax(scores,m).sum(m)==1  =>  out = (1+self_weight)*(x @ W).
// adj, att are dead inputs.
//
// R14: R12 (best: single-term fp16 HMMA, TM=64/TN=64, grid 256, occ 2,
// rel_err 2.92e-4) with critical-path trims:
//  - STS.128 staging (8 stores/thread instead of 16)
//  - B loaded/converted before A (B feeds 2/3 of ldsm traffic)
//  - explicit double-buffered ldsm->MMA pipeline in the k-loop

#define MDIM 8192
#define KDIM 128
#define NDIM 128
#define TM 64
#define TN 64
#define ASTRIDE 272   // A smem row: 128 fp16 = 256B data + 16 pad
#define BSTRIDE 144   // B smem row: 64 fp16 = 128B data + 16 pad

#define SMEM_A  0
#define SMEM_B  (SMEM_A + TM * ASTRIDE)         // 17408
#define SMEM_TOTAL (SMEM_B + KDIM * BSTRIDE)    // 35840

__device__ __forceinline__ uint32_t smem_u32(const void* p) {
    uint32_t a;
    asm("{ .reg .u64 t; cvta.to.shared.u64 t, %1; cvt.u32.u64 %0, t; }"
        : "=r"(a) : "l"(p));
    return a;
}

__device__ __forceinline__ void ldsm4(uint32_t r[4], uint32_t addr) {
    asm volatile("ldmatrix.sync.aligned.m8n8.x4.shared.b16 {%0,%1,%2,%3}, [%4];"
                 : "=r"(r[0]), "=r"(r[1]), "=r"(r[2]), "=r"(r[3]) : "r"(addr));
}
__device__ __forceinline__ void ldsm4t(uint32_t r[4], uint32_t addr) {
    asm volatile("ldmatrix.sync.aligned.m8n8.x4.trans.shared.b16 {%0,%1,%2,%3}, [%4];"
                 : "=r"(r[0]), "=r"(r[1]), "=r"(r[2]), "=r"(r[3]) : "r"(addr));
}

__device__ __forceinline__ void mma_f16(float c[4], const uint32_t a[4],
                                        uint32_t b0, uint32_t b1) {
    asm volatile(
        "mma.sync.aligned.m16n8k16.row.col.f32.f16.f16.f32 "
        "{%0,%1,%2,%3}, {%4,%5,%6,%7}, {%8,%9}, {%0,%1,%2,%3};"
        : "+f"(c[0]), "+f"(c[1]), "+f"(c[2]), "+f"(c[3])
        : "r"(a[0]), "r"(a[1]), "r"(a[2]), "r"(a[3]), "r"(b0), "r"(b1));
}

__device__ __forceinline__ uint32_t h2_pack(float a, float b) {
    __half2 h = __float22half2_rn(make_float2(a, b));
    return *reinterpret_cast<uint32_t*>(&h);
}
__device__ __forceinline__ uint4 cvt8(const float4& f0, const float4& f1) {
    uint4 v;
    v.x = h2_pack(f0.x, f0.y);
    v.y = h2_pack(f0.z, f0.w);
    v.z = h2_pack(f1.x, f1.y);
    v.w = h2_pack(f1.z, f1.w);
    return v;
}

__global__ __launch_bounds__(256, 2)
void gat_hmma_kernel(const float* __restrict__ x,
                     const float* __restrict__ W,
                     const float* __restrict__ self_weight,
                     float* __restrict__ out) {
    extern __shared__ char smem[];
    const uint32_t sbase = smem_u32(smem);
    const int tid = threadIdx.x;
    const int wid = tid >> 5;
    const int lid = tid & 31;

    const int bcol = blockIdx.x & 1;
    const int brow = blockIdx.x >> 1;
    const int row0 = brow * TM;
    const int col0 = bcol * TN;

    const float s = 1.0f + self_weight[0];

    // ---- batched loads: B first (feeds 2/3 of ldsm), then A; 16 in flight ----
    float4 fb[8], fa[8];
    #pragma unroll
    for (int r = 0; r < 4; r++) {
        int g  = tid + r * 256;            // 0..1023
        int k  = g >> 3;                   // 0..127
        int c8 = g & 7;                    // 8-float chunk within 64-col row
        const float* p = &W[(size_t)k * NDIM + col0 + c8 * 8];
        fb[2 * r]     = *(const float4*)p;
        fb[2 * r + 1] = *(const float4*)(p + 4);
    }
    #pragma unroll
    for (int r = 0; r < 4; r++) {
        int g  = tid + r * 256;            // 0..1023
        int m  = g >> 4;                   // 0..63
        int c8 = g & 15;                   // 8-float chunk within 128-col row
        const float* p = &x[(size_t)(row0 + m) * KDIM + c8 * 8];
        fa[2 * r]     = *(const float4*)p;
        fa[2 * r + 1] = *(const float4*)(p + 4);
    }

    // ---- convert + STS.128: B first ----
    #pragma unroll
    for (int r = 0; r < 4; r++) {
        int g  = tid + r * 256;
        int k  = g >> 3;
        int c8 = g & 7;
        *(uint4*)(smem + SMEM_B + k * BSTRIDE + c8 * 16) =
            cvt8(fb[2 * r], fb[2 * r + 1]);
    }
    #pragma unroll
    for (int r = 0; r < 4; r++) {
        int g  = tid + r * 256;
        int m  = g >> 4;
        int c8 = g & 15;
        *(uint4*)(smem + SMEM_A + m * ASTRIDE + c8 * 16) =
            cvt8(fa[2 * r], fa[2 * r + 1]);
    }
    __syncthreads();

    // ---- compute: warp tile 16 rows x 32 cols (4x2 warp grid) ----
    const int wm = (wid >> 1) * 16;     // 0,16,32,48
    const int wn = (wid & 1) * 32;      // 0,32

    float acc[4][4];
    #pragma unroll
    for (int j = 0; j < 4; j++)
        #pragma unroll
        for (int e = 0; e < 4; e++) acc[j][e] = 0.f;

    const uint32_t aAddr = sbase + SMEM_A
        + (wm + (lid & 15)) * ASTRIDE + 16 * (lid >> 4);
    uint32_t bAddr[2];
    #pragma unroll
    for (int p = 0; p < 2; p++)
        bAddr[p] = sbase + SMEM_B
            + (8 * ((lid >> 3) & 1) + (lid & 7)) * BSTRIDE
            + (wn + 16 * p + 8 * (lid >> 4)) * 2;

    // ---- double-buffered fragment pipeline ----
    uint32_t ah[2][4], bh[2][2][4];
    ldsm4(ah[0], aAddr);
    ldsm4t(bh[0][0], bAddr[0]);
    ldsm4t(bh[0][1], bAddr[1]);

    #pragma unroll
    for (int ks = 0; ks < 8; ks++) {
        const int cur = ks & 1, nxt = cur ^ 1;
        if (ks < 7) {
            const uint32_t ako = (ks + 1) * 32;
            const uint32_t bko = (ks + 1) * 16 * BSTRIDE;
            ldsm4(ah[nxt], aAddr + ako);
            ldsm4t(bh[nxt][0], bAddr[0] + bko);
            ldsm4t(bh[nxt][1], bAddr[1] + bko);
        }
        #pragma unroll
        for (int nt = 0; nt < 4; nt++) {
            const int p = nt >> 1, q = (nt & 1) * 2;
            mma_f16(acc[nt], ah[cur], bh[cur][p][q], bh[cur][p][q + 1]);
        }
    }

    // ---- epilogue: scale, store ----
    #pragma unroll
    for (int nt = 0; nt < 4; nt++) {
        const int r0 = row0 + wm + (lid >> 2);
        const int c  = col0 + wn + 8 * nt + 2 * (lid & 3);
        float2 s0 = {acc[nt][0] * s, acc[nt][1] * s};
        float2 s1 = {acc[nt][2] * s, acc[nt][3] * s};
        *(float2*)&out[(size_t)r0 * NDIM + c]       = s0;
        *(float2*)&out[(size_t)(r0 + 8) * NDIM + c] = s1;
    }
}

extern "C" void kernel_launch(void* const* d_in, const int* in_sizes, int n_in,
                              void* d_out, int out_size) {
    // metadata order: x, adj (UNUSED), W, att (UNUSED), self_weight
    const float* x  = (const float*)d_in[0];
    const float* W  = (const float*)d_in[2];
    const float* sw = (const float*)d_in[4];
    float* out      = (float*)d_out;

    dim3 grid((MDIM / TM) * (NDIM / TN));         // 128 * 2 = 256 blocks
    gat_hmma_kernel<<<grid, 256, SMEM_TOTAL>>>(x, W, sw, out);
}

// round 15
// speedup vs baseline: 1.3413x; 1.3413x over previous
#include <cuda_runtime.h>
#include <cuda_fp16.h>
#include <cstdint>

// Problem (fixed): B=4,N=2048,Fin=128,H=4,Fout=32.
// Identity: softmax(scores,m).sum(m)==1  =>  out = (1+self_weight)*(x @ W).
// adj, att are dead inputs.
//
// R15 == R12 (confirmed best): single-term fp16 HMMA,
// out ~= fp16(x) @ fp16(W) with fp32 accumulate, rel_err 2.92e-4.
// TM=64, TN=64, 256 thr, warp tile 16x32, grid 256, occ 2.
// R14's STS.128 + explicit ldsm double-buffer trims regressed (bank overlap
// on the 68-word row stride + register pressure) -- reverted.

#define MDIM 8192
#define KDIM 128
#define NDIM 128
#define TM 64
#define TN 64
#define ASTRIDE 272   // A smem row: 128 fp16 = 256B data + 16 pad
#define BSTRIDE 144   // B smem row: 64 fp16 = 128B data + 16 pad

#define SMEM_A  0
#define SMEM_B  (SMEM_A + TM * ASTRIDE)         // 17408
#define SMEM_TOTAL (SMEM_B + KDIM * BSTRIDE)    // 35840

__device__ __forceinline__ uint32_t smem_u32(const void* p) {
    uint32_t a;
    asm("{ .reg .u64 t; cvta.to.shared.u64 t, %1; cvt.u32.u64 %0, t; }"
        : "=r"(a) : "l"(p));
    return a;
}

__device__ __forceinline__ void ldsm4(uint32_t r[4], uint32_t addr) {
    asm volatile("ldmatrix.sync.aligned.m8n8.x4.shared.b16 {%0,%1,%2,%3}, [%4];"
                 : "=r"(r[0]), "=r"(r[1]), "=r"(r[2]), "=r"(r[3]) : "r"(addr));
}
__device__ __forceinline__ void ldsm4t(uint32_t r[4], uint32_t addr) {
    asm volatile("ldmatrix.sync.aligned.m8n8.x4.trans.shared.b16 {%0,%1,%2,%3}, [%4];"
                 : "=r"(r[0]), "=r"(r[1]), "=r"(r[2]), "=r"(r[3]) : "r"(addr));
}

__device__ __forceinline__ void mma_f16(float c[4], const uint32_t a[4],
                                        uint32_t b0, uint32_t b1) {
    asm volatile(
        "mma.sync.aligned.m16n8k16.row.col.f32.f16.f16.f32 "
        "{%0,%1,%2,%3}, {%4,%5,%6,%7}, {%8,%9}, {%0,%1,%2,%3};"
        : "+f"(c[0]), "+f"(c[1]), "+f"(c[2]), "+f"(c[3])
        : "r"(a[0]), "r"(a[1]), "r"(a[2]), "r"(a[3]), "r"(b0), "r"(b1));
}

__device__ __forceinline__ uint32_t h2_pack(float a, float b) {
    __half2 h = __float22half2_rn(make_float2(a, b));
    return *reinterpret_cast<uint32_t*>(&h);
}
__device__ __forceinline__ uint2 cvt4(const float4& f) {
    uint2 r;
    r.x = h2_pack(f.x, f.y);
    r.y = h2_pack(f.z, f.w);
    return r;
}

__global__ __launch_bounds__(256, 2)
void gat_hmma_kernel(const float* __restrict__ x,
                     const float* __restrict__ W,
                     const float* __restrict__ self_weight,
                     float* __restrict__ out) {
    extern __shared__ char smem[];
    const uint32_t sbase = smem_u32(smem);
    const int tid = threadIdx.x;
    const int wid = tid >> 5;
    const int lid = tid & 31;

    const int bcol = blockIdx.x & 1;
    const int brow = blockIdx.x >> 1;
    const int row0 = brow * TM;
    const int col0 = bcol * TN;

    const float s = 1.0f + self_weight[0];

    // ---- batched loads: all 16 LDG.128 in flight before any convert ----
    float4 fa[8], fb[8];
    #pragma unroll
    for (int r = 0; r < 8; r++) {
        int g  = tid + r * 256;
        int m  = g >> 5;                  // 0..63
        int k4 = g & 31;
        fa[r] = *(const float4*)&x[(size_t)(row0 + m) * KDIM + k4 * 4];
    }
    #pragma unroll
    for (int r = 0; r < 8; r++) {
        int g  = tid + r * 256;
        int k  = g >> 4;                  // 0..127
        int n4 = g & 15;
        fb[r] = *(const float4*)&W[(size_t)k * NDIM + col0 + n4 * 4];
    }

    // ---- convert + store A (single fp16) ----
    #pragma unroll
    for (int r = 0; r < 8; r++) {
        int g  = tid + r * 256;
        int m  = g >> 5;
        int k4 = g & 31;
        *(uint2*)(smem + SMEM_A + m * ASTRIDE + k4 * 8) = cvt4(fa[r]);
    }
    // ---- convert + store B (single fp16) ----
    #pragma unroll
    for (int r = 0; r < 8; r++) {
        int g  = tid + r * 256;
        int k  = g >> 4;
        int n4 = g & 15;
        *(uint2*)(smem + SMEM_B + k * BSTRIDE + n4 * 8) = cvt4(fb[r]);
    }
    __syncthreads();

    // ---- compute: warp tile 16 rows x 32 cols (4x2 warp grid) ----
    const int wm = (wid >> 1) * 16;     // 0,16,32,48
    const int wn = (wid & 1) * 32;      // 0,32

    float acc[4][4];
    #pragma unroll
    for (int j = 0; j < 4; j++)
        #pragma unroll
        for (int e = 0; e < 4; e++) acc[j][e] = 0.f;

    // A x4 (non-trans) from [m][k]
    const uint32_t aAddr = sbase + SMEM_A
        + (wm + (lid & 15)) * ASTRIDE + 16 * (lid >> 4);
    // B x4 trans from [k][n]
    uint32_t bAddr[2];
    #pragma unroll
    for (int p = 0; p < 2; p++)
        bAddr[p] = sbase + SMEM_B
            + (8 * ((lid >> 3) & 1) + (lid & 7)) * BSTRIDE
            + (wn + 16 * p + 8 * (lid >> 4)) * 2;

    #pragma unroll
    for (int ks = 0; ks < 8; ks++) {
        const uint32_t ako = ks * 32;            // 16 fp16 along A row
        const uint32_t bko = ks * 16 * BSTRIDE;  // 16 k-rows down B tile

        uint32_t ah[4];
        ldsm4(ah, aAddr + ako);

        uint32_t bh[2][4];
        #pragma unroll
        for (int p = 0; p < 2; p++)
            ldsm4t(bh[p], bAddr[p] + bko);

        #pragma unroll
        for (int nt = 0; nt < 4; nt++) {
            const int p = nt >> 1, q = (nt & 1) * 2;
            mma_f16(acc[nt], ah, bh[p][q], bh[p][q + 1]);
        }
    }

    // ---- epilogue: scale, store ----
    #pragma unroll
    for (int nt = 0; nt < 4; nt++) {
        const int r0 = row0 + wm + (lid >> 2);
        const int c  = col0 + wn + 8 * nt + 2 * (lid & 3);
        float2 s0 = {acc[nt][0] * s, acc[nt][1] * s};
        float2 s1 = {acc[nt][2] * s, acc[nt][3] * s};
        *(float2*)&out[(size_t)r0 * NDIM + c]       = s0;
        *(float2*)&out[(size_t)(r0 + 8) * NDIM + c] = s1;
    }
}

extern "C" void kernel_launch(void* const* d_in, const int* in_sizes, int n_in,
                              void* d_out, int out_size) {
    // metadata order: x, adj (UNUSED), W, att (UNUSED), self_weight
    const float* x  = (const float*)d_in[0];
    const float* W  = (const float*)d_in[2];
    const float* sw = (const float*)d_in[4];
    float* out      = (float*)d_out;

    cudaFuncSetAttribute(gat_hmma_kernel,
                         cudaFuncAttributeMaxDynamicSharedMemorySize, SMEM_TOTAL);

    dim3 grid((MDIM / TM) * (NDIM / TN));         // 128 * 2 = 256 blocks
    gat_hmma_kernel<<<grid, 256, SMEM_TOTAL>>>(x, W, sw, out);
}